// round 14
// baseline (speedup 1.0000x reference)
#include <cuda_runtime.h>
#include <math.h>

#define BB 32
#define SS 512
#define HH 768
#define WE 150
#define LL 9
#define NPOS (BB*SS)            // 16384
#define NSPANS (BB*4096)        // 131072
#define T_STRIDE 304            // [0:150]=start part, [152:302]=end part
#define WD_STRIDE 152
#define RANKCAP 32
#define KEYS_PER_B (RANKCAP*RANKCAP*9)   // 9216
#define NKEYS (BB*KEYS_PER_B)            // 294912
#define TROWS 8
#define KCH 24
#define KSP 8                    // k split: 8 tasks x 96
#define UT 128

typedef unsigned long long ull;

// static scratch; zero-initialized at load; pipeline restores entry state each call.
__device__ float    g_T[NPOS*T_STRIDE];
__device__ float    g_WD[16*WD_STRIDE];
__device__ float    g_ULOG[(size_t)NSPANS*12];   // [0:9)=logits, [9]=lse
__device__ int      g_used[NPOS];       // cleared by k_compact after read
__device__ int      g_list[NPOS];
__device__ int      g_slotOfPos[NPOS];
__device__ int      g_rank[NPOS];
__device__ int      g_bcount[BB];       // reset by k_scatter
__device__ int      g_count;            // reset by k_scatter
__device__ int      g_ckey[NKEYS];      // 0=empty, owner=i+1; cleared by k_scatter
__device__ int      g_uslot[NKEYS];
__device__ int      g_key[NSPANS];
__device__ int      g_spanslot[NSPANS];
__device__ unsigned g_uinfo[NSPANS];
__device__ int      g_ucount;           // reset by k_scatter
__device__ int      g_tile;             // uniq work-steal; reset by k_scatter

__device__ __forceinline__ int clampi(int v, int lo, int hi) { return min(max(v, lo), hi); }

__device__ __forceinline__ ull ffma2(ull a, ull b, ull c) {
    ull d;
    asm("fma.rn.f32x2 %0, %1, %2, %3;" : "=l"(d) : "l"(a), "l"(b), "l"(c));
    return d;
}
__device__ __forceinline__ ull pack2(float x) {
    ull d;
    asm("mov.b64 %0, {%1, %1};" : "=l"(d) : "f"(x));
    return d;
}
__device__ __forceinline__ void unpack2(ull v, float& lo, float& hi) {
    asm("mov.b64 {%0, %1}, %2;" : "=f"(lo), "=f"(hi) : "l"(v));
}

// K1: mark used positions + zero loss
__global__ void k_mark(const int* __restrict__ spans, float* __restrict__ loss_ptr) {
    int i = blockIdx.x * blockDim.x + threadIdx.x;
    if (i == 0) *loss_ptr = 0.f;
    if (i >= NSPANS) return;
    int b = i >> 12;
    int s = clampi(spans[3*i], 0, SS-1);
    int e = clampi(spans[3*i + 1], 0, SS-1);
    g_used[(b << 9) + s] = 1;
    g_used[(b << 9) + e] = 1;
}

// K2: compact used positions (and self-clear g_used)
__global__ void k_compact() {
    int i = blockIdx.x * blockDim.x + threadIdx.x;
    if (i >= NPOS) return;
    if (g_used[i]) {
        int slot = atomicAdd(&g_count, 1);
        g_list[slot] = i;
        g_slotOfPos[i] = slot;
        g_rank[i] = atomicAdd(&g_bcount[i >> 9], 1);
        g_used[i] = 0;
    }
}

// K3: blocks [0,512): claim; blocks [512,544): zero g_T rows
__global__ void k_claim(const int* __restrict__ spans) {
    int bi = blockIdx.x;
    int tid = threadIdx.x;
    if (bi < 512) {
        int i = bi * 256 + tid;
        int b = i >> 12;
        int si = clampi(spans[3*i], 0, SS-1);
        int ei = clampi(spans[3*i + 1], 0, SS-1);
        int wi = clampi(spans[3*i + 2], 0, 8);
        int rs = g_rank[(b << 9) + si];
        int re = g_rank[(b << 9) + ei];
        int key = -2;
        bool own;
        if (rs < RANKCAP && re < RANKCAP) {
            key = b * KEYS_PER_B + (rs * RANKCAP + re) * 9 + wi;
            own = (atomicCAS(&g_ckey[key], 0, i + 1) == 0);
        } else {
            own = true;
        }
        g_key[i] = key;
        if (own) {
            int ss = g_slotOfPos[(b << 9) + si];
            int se = g_slotOfPos[(b << 9) + ei];
            int slot = atomicAdd(&g_ucount, 1);
            g_uinfo[slot] = (unsigned)ss | ((unsigned)se << 14) | ((unsigned)wi << 28);
            if (key >= 0) g_uslot[key] = slot;
            else g_spanslot[i] = slot;
        }
    } else {
        int cnt = g_count;
        for (int slot = bi - 512; slot < cnt; slot += 32) {
            float4* tz = (float4*)(g_T + (size_t)slot * T_STRIDE);
            for (int t = tid; t < T_STRIDE/4; t += 256)
                tz[t] = make_float4(0.f, 0.f, 0.f, 0.f);
        }
    }
}

// K4: T projection (rowtile 8 x ksplit 8), 2 CTAs/SM — unchanged from R12.
__global__ void __launch_bounds__(300, 2)
k_TgemmWD(const float* __restrict__ seq, const float* __restrict__ W1,
          const float* __restrict__ wt, const float* __restrict__ b1) {
    extern __shared__ float smem[];
    float* sW  = smem;                      // [2][KCH][304]
    float* sA  = smem + 2*KCH*304;          // [96][8] k-major
    int*  sRow = (int*)(sA + 96*TROWS);     // [8]
    float* sRed = (float*)(sRow + 8);       // [160]

    int cnt = g_count;
    int nrt = (cnt + TROWS - 1) / TROWS;
    int ngemm = nrt * KSP;
    int ntasks = ngemm + 9;
    int tid = threadIdx.x;
    int cp = tid % 150;
    int rg = tid / 150;
    int jj = 2 * cp;
    int col0 = (jj < 150) ? jj : (jj + 2);

    for (int task = blockIdx.x; task < ntasks; task += gridDim.x) {
        if (task < ngemm) {
            int rt = task >> 3, ks = task & 7;
            int r0 = rt * TROWS, k0 = ks * 96;

            if (tid < TROWS) sRow[tid] = g_list[min(r0 + tid, cnt - 1)];
            __syncthreads();

            for (int idx = tid; idx < 96 * TROWS; idx += 300) {
                int k = idx >> 3, r = idx & 7;
                sA[idx] = fmaxf(seq[(size_t)sRow[r] * HH + k0 + k], 0.f);
            }
            {
                const float* src = (tid < 150)
                    ? (W1 + (size_t)k0 * WE + tid)
                    : (W1 + (size_t)(HH + k0) * WE + (tid - 150));
                #pragma unroll
                for (int kk = 0; kk < KCH; kk++)
                    sW[kk * 304 + tid] = src[(size_t)kk * WE];
            }
            __syncthreads();

            ull acc00 = 0ull, acc01 = 0ull, acc10 = 0ull, acc11 = 0ull;

            #pragma unroll 1
            for (int c = 0; c < 4; c++) {
                if (c + 1 < 4) {
                    int kb = k0 + (c + 1) * KCH;
                    const float* src = (tid < 150)
                        ? (W1 + (size_t)kb * WE + tid)
                        : (W1 + (size_t)(HH + kb) * WE + (tid - 150));
                    float* dst = sW + ((c + 1) & 1) * KCH * 304;
                    #pragma unroll
                    for (int kk = 0; kk < KCH; kk++)
                        dst[kk * 304 + tid] = src[(size_t)kk * WE];
                }
                {
                    const float* wb = sW + (c & 1) * KCH * 304;
                    const float* ab = sA + c * KCH * TROWS + rg * 4;
                    #pragma unroll
                    for (int kk = 0; kk < KCH; kk++) {
                        ull wpair = *(const ull*)&wb[kk * 304 + jj];
                        float wx, wy;
                        unpack2(wpair, wx, wy);
                        ull b0 = pack2(wx), b1v = pack2(wy);
                        ull a0 = *(const ull*)&ab[kk * TROWS];
                        ull a1 = *(const ull*)&ab[kk * TROWS + 2];
                        acc00 = ffma2(a0, b0,  acc00);
                        acc01 = ffma2(a0, b1v, acc01);
                        acc10 = ffma2(a1, b0,  acc10);
                        acc11 = ffma2(a1, b1v, acc11);
                    }
                }
                __syncthreads();
            }

            {
                int rbase = r0 + rg * 4;
                ull accs[2][2] = {{acc00, acc01}, {acc10, acc11}};
                #pragma unroll
                for (int p = 0; p < 2; p++) {
                    int rA = rbase + 2 * p;
                    #pragma unroll
                    for (int cc = 0; cc < 2; cc++) {
                        float lo, hi;
                        unpack2(accs[p][cc], lo, hi);
                        if (rA < cnt)
                            atomicAdd(&g_T[(size_t)rA * T_STRIDE + col0 + cc], lo);
                        if (rA + 1 < cnt)
                            atomicAdd(&g_T[(size_t)(rA + 1) * T_STRIDE + col0 + cc], hi);
                    }
                }
            }
            __syncthreads();
        } else {
            int w = task - ngemm;   // 0..8
            for (int t = tid; t < 150; t += 300) sA[t] = fmaxf(wt[w*150 + t], 0.f);
            __syncthreads();
            int g = tid / 150;
            int j = tid - g * 150;
            float acc = (g == 0) ? b1[j] : 0.f;
            int kst = g * 75;
            #pragma unroll 8
            for (int k = kst; k < kst + 75; k++)
                acc = fmaf(sA[k], W1[(size_t)(2*HH + k) * WE + j], acc);
            if (g == 1) sRed[j] = acc;
            __syncthreads();
            if (g == 0) g_WD[w * WD_STRIDE + j] = acc + sRed[j];
            __syncthreads();
        }
    }
}

// K5: unique rows -> h1 -> @W2+b2 (FFMA2) -> @W3+b3 -> logits + lse.
// 512 threads, 128-row tiles: 16 warps/SM hide LDS latency; B-operand LDS
// is warp-uniform (c0 = (tid>>5)*10). Work-stealing tiles.
// smem layout (floats):
//   sW2   [0, 24000)      [150][160]
//   sU    [24000, 45000)  h1T [152][128] (19456) / h2 [128][164] (20992)
//   sW3   [45000, 46800)  [150][12]
//   sB2   [46800, 46960)
//   sB3   [46960, 46972)
//   sInfo [46972, 47100)  [128] unsigned
//   sTile [47100]
//   sLg   [47104, 48640)  [128][12]
__global__ void __launch_bounds__(512, 1)
k_uniq(const float* __restrict__ W2, const float* __restrict__ b2,
       const float* __restrict__ W3, const float* __restrict__ b3)
{
    extern __shared__ float sm[];
    float* sW2 = sm;
    float* sU  = sm + 24000;
    float* sW3 = sm + 45000;
    float* sB2 = sm + 46800;
    float* sB3 = sm + 46960;
    unsigned* sInfo = (unsigned*)(sm + 46972);
    int* sTile = (int*)(sm + 47100);
    float* sLg = sm + 47104;
    int tid = threadIdx.x;

    for (int idx = tid; idx < 150*160; idx += 512) {
        int k = idx / 160, j = idx - k*160;
        sW2[idx] = (j < 150) ? W2[k*150 + j] : 0.f;
    }
    for (int idx = tid; idx < 150*12; idx += 512) {
        int k = idx / 12, l = idx - k*12;
        sW3[idx] = (l < 9) ? W3[k*9 + l] : 0.f;
    }
    if (tid < 160) sB2[tid] = (tid < 150) ? b2[tid] : 0.f;
    if (tid >= 160 && tid < 172) sB3[tid - 160] = (tid - 160 < 9) ? b3[tid - 160] : 0.f;

    int nu = g_ucount;
    int r0 = (tid & 31) * 4;     // 4 consecutive rows (0..124)
    int c0 = (tid >> 5) * 10;    // warp-uniform column group

    for (;;) {
        if (tid == 0) *sTile = atomicAdd(&g_tile, 1);
        __syncthreads();
        int base = (*sTile) * UT;
        if (base >= nu) break;

        if (tid < UT)
            sInfo[tid] = (base + tid < nu) ? g_uinfo[base + tid] : 0u;
        __syncthreads();

        // gather h1, k-major [k][128], float4 over k
        for (int idx = tid; idx < 38*UT; idx += 512) {
            int kq = idx >> 7, r = idx & 127;
            unsigned info = sInfo[r];
            int ss = info & 0x3FFF, se = (info >> 14) & 0x3FFF, w = info >> 28;
            float4 ts = *(const float4*)&g_T[(size_t)ss*T_STRIDE + kq*4];
            float4 te = *(const float4*)&g_T[(size_t)se*T_STRIDE + 152 + kq*4];
            float4 wd = *(const float4*)&g_WD[w*WD_STRIDE + kq*4];
            sU[(kq*4 + 0)*UT + r] = fmaxf(ts.x + te.x + wd.x, 0.f);
            sU[(kq*4 + 1)*UT + r] = fmaxf(ts.y + te.y + wd.y, 0.f);
            sU[(kq*4 + 2)*UT + r] = fmaxf(ts.z + te.z + wd.z, 0.f);
            sU[(kq*4 + 3)*UT + r] = fmaxf(ts.w + te.w + wd.w, 0.f);
        }
        __syncthreads();

        // h2 = h1 @ W2 + b2, packed column pairs (FFMA2)
        ull acc[4][5];
        {
            const ull* bp = (const ull*)&sB2[c0];
            #pragma unroll
            for (int p = 0; p < 5; p++) {
                ull bv = bp[p];
                #pragma unroll
                for (int ri = 0; ri < 4; ri++) acc[ri][p] = bv;
            }
        }
        #pragma unroll 2
        for (int k = 0; k < 150; k++) {
            float4 a = *(const float4*)&sU[k*UT + r0];
            ull ap[4] = {pack2(a.x), pack2(a.y), pack2(a.z), pack2(a.w)};
            const ull* bw = (const ull*)&sW2[k*160 + c0];
            ull bv[5] = {bw[0], bw[1], bw[2], bw[3], bw[4]};
            #pragma unroll
            for (int ri = 0; ri < 4; ri++)
                #pragma unroll
                for (int p = 0; p < 5; p++)
                    acc[ri][p] = ffma2(ap[ri], bv[p], acc[ri][p]);
        }
        __syncthreads();   // all h1 reads done before overwriting sU

        #pragma unroll
        for (int ri = 0; ri < 4; ri++)
            #pragma unroll
            for (int p = 0; p < 5; p++)
                *(ull*)&sU[(r0 + ri)*164 + c0 + 2*p] = acc[ri][p];
        __syncthreads();

        // logits = h2 @ W3 + b3 (also staged to sLg for lse)
        for (int idx = tid; idx < UT*LL; idx += 512) {
            int r = idx / LL, l = idx - r*LL;
            float a = sB3[l];
            #pragma unroll 5
            for (int k = 0; k < 150; k++)
                a = fmaf(sU[r*164 + k], sW3[k*12 + l], a);
            sLg[r*12 + l] = a;
            if (base + r < nu)
                g_ULOG[(size_t)(base + r)*12 + l] = a;
        }
        __syncthreads();

        // lse per unique row
        if (tid < UT && base + tid < nu) {
            float m = sLg[tid*12];
            #pragma unroll
            for (int l = 1; l < LL; l++) m = fmaxf(m, sLg[tid*12 + l]);
            float ssum = 0.f;
            #pragma unroll
            for (int l = 0; l < LL; l++) ssum += expf(sLg[tid*12 + l] - m);
            g_ULOG[(size_t)(base + tid)*12 + 9] = m + logf(ssum);
        }
        __syncthreads();
    }
}

// K6: scatter logits per span + NLL via precomputed lse + restore state
__global__ void k_scatter(const int* __restrict__ mask,
                          const int* __restrict__ label,
                          float* __restrict__ out)
{
    __shared__ float sL;
    if (threadIdx.x == 0) sL = 0.f;
    __syncthreads();
    int i = blockIdx.x * blockDim.x + threadIdx.x;
    float contrib = 0.f;
    if (i < NSPANS) {
        int key = g_key[i];
        int slot;
        if (key >= 0) { slot = g_uslot[key]; g_ckey[key] = 0; }
        else          { slot = g_spanslot[i]; }
        const float* Lr = &g_ULOG[(size_t)slot * 12];
        float4 p0 = *(const float4*)Lr;
        float4 p1 = *(const float4*)(Lr + 4);
        float2 p2 = *(const float2*)(Lr + 8);   // [8]=logit8, [9]=lse
        float L[9] = {p0.x, p0.y, p0.z, p0.w, p1.x, p1.y, p1.z, p1.w, p2.x};
        float* o = out + (size_t)i * LL;
        #pragma unroll
        for (int l = 0; l < LL; l++) o[l] = L[l];
        if (mask[i] == 1) {
            int lb = clampi(label[i], 0, LL-1);
            contrib = p2.y - L[lb];
        }
    }
    atomicAdd(&sL, contrib);
    __syncthreads();
    if (threadIdx.x == 0 && sL != 0.f)
        atomicAdd(&out[(size_t)NSPANS * LL], sL);
    if (blockIdx.x == 0 && threadIdx.x == 0) {
        g_count = 0; g_ucount = 0; g_tile = 0;
        #pragma unroll
        for (int w = 0; w < BB; w++) g_bcount[w] = 0;
    }
}

extern "C" void kernel_launch(void* const* d_in, const int* in_sizes, int n_in,
                              void* d_out, int out_size) {
    const float* seq = (const float*)d_in[0];
    const float* wt  = (const float*)d_in[1];
    const float* W1  = (const float*)d_in[2];
    const float* b1  = (const float*)d_in[3];
    const float* W2  = (const float*)d_in[4];
    const float* b2  = (const float*)d_in[5];
    const float* W3  = (const float*)d_in[6];
    const float* b3  = (const float*)d_in[7];
    const int* spans = (const int*)d_in[8];
    const int* smask = (const int*)d_in[9];
    const int* slab  = (const int*)d_in[10];
    float* out = (float*)d_out;

    static const size_t SMEM_UNIQ = (size_t)48640 * 4;   // 194560 B
    static const size_t SMEM_TG   = (size_t)(2*KCH*304 + 96*TROWS + 8 + 160 + 8) * 4;
    cudaFuncSetAttribute(k_uniq, cudaFuncAttributeMaxDynamicSharedMemorySize, (int)SMEM_UNIQ);
    cudaFuncSetAttribute(k_TgemmWD, cudaFuncAttributeMaxDynamicSharedMemorySize, (int)SMEM_TG);

    k_mark<<<NSPANS/256, 256>>>(spans, out + (size_t)NSPANS * LL);
    k_compact<<<NPOS/256, 256>>>();
    k_claim<<<544, 256>>>(spans);
    k_TgemmWD<<<296, 300, SMEM_TG>>>(seq, W1, wt, b1);
    k_uniq<<<148, 512, SMEM_UNIQ>>>(W2, b2, W3, b3);
    k_scatter<<<NSPANS/256, 256>>>(smask, slab, out);
}

// round 15
// speedup vs baseline: 1.7319x; 1.7319x over previous
#include <cuda_runtime.h>
#include <math.h>

#define BB 32
#define SS 512
#define HH 768
#define WE 150
#define LL 9
#define NPOS (BB*SS)            // 16384
#define NSPANS (BB*4096)        // 131072
#define T_STRIDE 304            // [0:150]=start part, [152:302]=end part
#define WD_STRIDE 152
#define RANKCAP 32
#define KEYS_PER_B (RANKCAP*RANKCAP*9)   // 9216
#define NKEYS (BB*KEYS_PER_B)            // 294912
#define TROWS 8
#define KCH 24
#define KSP 8                    // k split: 8 tasks x 96
#define UT 64

typedef unsigned long long ull;

// static scratch; zero-initialized at load; pipeline restores entry state each call.
__device__ float    g_T[NPOS*T_STRIDE];
__device__ float    g_WD[16*WD_STRIDE];
__device__ float    g_W23[152*12];      // W2@W3, [k][l] stride 12 (l>=9 stay 0)
__device__ float    g_b23[12];          // b2@W3 + b3
__device__ float    g_ULOG[(size_t)NSPANS*12];   // [0:9)=logits, [9]=lse
__device__ int      g_used[NPOS];       // cleared by k_compact after read
__device__ int      g_list[NPOS];
__device__ int      g_slotOfPos[NPOS];
__device__ int      g_rank[NPOS];
__device__ int      g_bcount[BB];       // reset by k_scatter
__device__ int      g_count;            // reset by k_scatter
__device__ int      g_ckey[NKEYS];      // 0=empty, owner=i+1; cleared by k_scatter
__device__ int      g_uslot[NKEYS];
__device__ int      g_key[NSPANS];
__device__ int      g_spanslot[NSPANS];
__device__ unsigned g_uinfo[NSPANS];
__device__ int      g_ucount;           // reset by k_scatter
__device__ int      g_tile;             // uniq work-steal; reset by k_scatter

__device__ __forceinline__ int clampi(int v, int lo, int hi) { return min(max(v, lo), hi); }

__device__ __forceinline__ ull ffma2(ull a, ull b, ull c) {
    ull d;
    asm("fma.rn.f32x2 %0, %1, %2, %3;" : "=l"(d) : "l"(a), "l"(b), "l"(c));
    return d;
}
__device__ __forceinline__ ull pack2(float x) {
    ull d;
    asm("mov.b64 %0, {%1, %1};" : "=l"(d) : "f"(x));
    return d;
}
__device__ __forceinline__ void unpack2(ull v, float& lo, float& hi) {
    asm("mov.b64 {%0, %1}, %2;" : "=f"(lo), "=f"(hi) : "l"(v));
}

// K1: blocks [0,512): mark used positions + zero loss
//     blocks [512,527): W23 = W2@W3 (10 k-rows per block)
//     block  527:       b23 = b2@W3 + b3
__global__ void k_mark(const int* __restrict__ spans,
                       const float* __restrict__ W2, const float* __restrict__ W3,
                       const float* __restrict__ b2, const float* __restrict__ b3,
                       float* __restrict__ loss_ptr) {
    __shared__ float sW3s[1360];
    int bi = blockIdx.x;
    int tid = threadIdx.x;
    if (bi < 512) {
        int i = bi * 256 + tid;
        if (i == 0) *loss_ptr = 0.f;
        int b = i >> 12;
        int s = clampi(spans[3*i], 0, SS-1);
        int e = clampi(spans[3*i + 1], 0, SS-1);
        g_used[(b << 9) + s] = 1;
        g_used[(b << 9) + e] = 1;
    } else {
        for (int t = tid; t < 150*LL; t += 256) sW3s[t] = W3[t];
        __syncthreads();
        if (bi < 527) {
            if (tid < 90) {
                int k = (bi - 512) * 10 + tid / 9;
                int l = tid - (tid / 9) * 9;
                float acc = 0.f;
                #pragma unroll 10
                for (int j = 0; j < 150; j++)
                    acc = fmaf(W2[k*150 + j], sW3s[j*9 + l], acc);
                g_W23[k*12 + l] = acc;
            }
        } else {
            if (tid < 9) {
                float acc = b3[tid];
                #pragma unroll 10
                for (int j = 0; j < 150; j++)
                    acc = fmaf(b2[j], sW3s[j*9 + tid], acc);
                g_b23[tid] = acc;
            }
        }
    }
}

// K2: compact used positions (and self-clear g_used)
__global__ void k_compact() {
    int i = blockIdx.x * blockDim.x + threadIdx.x;
    if (i >= NPOS) return;
    if (g_used[i]) {
        int slot = atomicAdd(&g_count, 1);
        g_list[slot] = i;
        g_slotOfPos[i] = slot;
        g_rank[i] = atomicAdd(&g_bcount[i >> 9], 1);
        g_used[i] = 0;
    }
}

// K3: blocks [0,512): claim; blocks [512,544): zero g_T rows
__global__ void k_claim(const int* __restrict__ spans) {
    int bi = blockIdx.x;
    int tid = threadIdx.x;
    if (bi < 512) {
        int i = bi * 256 + tid;
        int b = i >> 12;
        int si = clampi(spans[3*i], 0, SS-1);
        int ei = clampi(spans[3*i + 1], 0, SS-1);
        int wi = clampi(spans[3*i + 2], 0, 8);
        int rs = g_rank[(b << 9) + si];
        int re = g_rank[(b << 9) + ei];
        int key = -2;
        bool own;
        if (rs < RANKCAP && re < RANKCAP) {
            key = b * KEYS_PER_B + (rs * RANKCAP + re) * 9 + wi;
            own = (atomicCAS(&g_ckey[key], 0, i + 1) == 0);
        } else {
            own = true;
        }
        g_key[i] = key;
        if (own) {
            int ss = g_slotOfPos[(b << 9) + si];
            int se = g_slotOfPos[(b << 9) + ei];
            int slot = atomicAdd(&g_ucount, 1);
            g_uinfo[slot] = (unsigned)ss | ((unsigned)se << 14) | ((unsigned)wi << 28);
            if (key >= 0) g_uslot[key] = slot;
            else g_spanslot[i] = slot;
        }
    } else {
        int cnt = g_count;
        for (int slot = bi - 512; slot < cnt; slot += 32) {
            float4* tz = (float4*)(g_T + (size_t)slot * T_STRIDE);
            for (int t = tid; t < T_STRIDE/4; t += 256)
                tz[t] = make_float4(0.f, 0.f, 0.f, 0.f);
        }
    }
}

// K4: T projection (rowtile 8 x ksplit 8), 2 CTAs/SM — unchanged from R12.
__global__ void __launch_bounds__(300, 2)
k_TgemmWD(const float* __restrict__ seq, const float* __restrict__ W1,
          const float* __restrict__ wt, const float* __restrict__ b1) {
    extern __shared__ float smem[];
    float* sW  = smem;                      // [2][KCH][304]
    float* sA  = smem + 2*KCH*304;          // [96][8] k-major
    int*  sRow = (int*)(sA + 96*TROWS);     // [8]
    float* sRed = (float*)(sRow + 8);       // [160]

    int cnt = g_count;
    int nrt = (cnt + TROWS - 1) / TROWS;
    int ngemm = nrt * KSP;
    int ntasks = ngemm + 9;
    int tid = threadIdx.x;
    int cp = tid % 150;
    int rg = tid / 150;
    int jj = 2 * cp;
    int col0 = (jj < 150) ? jj : (jj + 2);

    for (int task = blockIdx.x; task < ntasks; task += gridDim.x) {
        if (task < ngemm) {
            int rt = task >> 3, ks = task & 7;
            int r0 = rt * TROWS, k0 = ks * 96;

            if (tid < TROWS) sRow[tid] = g_list[min(r0 + tid, cnt - 1)];
            __syncthreads();

            for (int idx = tid; idx < 96 * TROWS; idx += 300) {
                int k = idx >> 3, r = idx & 7;
                sA[idx] = fmaxf(seq[(size_t)sRow[r] * HH + k0 + k], 0.f);
            }
            {
                const float* src = (tid < 150)
                    ? (W1 + (size_t)k0 * WE + tid)
                    : (W1 + (size_t)(HH + k0) * WE + (tid - 150));
                #pragma unroll
                for (int kk = 0; kk < KCH; kk++)
                    sW[kk * 304 + tid] = src[(size_t)kk * WE];
            }
            __syncthreads();

            ull acc00 = 0ull, acc01 = 0ull, acc10 = 0ull, acc11 = 0ull;

            #pragma unroll 1
            for (int c = 0; c < 4; c++) {
                if (c + 1 < 4) {
                    int kb = k0 + (c + 1) * KCH;
                    const float* src = (tid < 150)
                        ? (W1 + (size_t)kb * WE + tid)
                        : (W1 + (size_t)(HH + kb) * WE + (tid - 150));
                    float* dst = sW + ((c + 1) & 1) * KCH * 304;
                    #pragma unroll
                    for (int kk = 0; kk < KCH; kk++)
                        dst[kk * 304 + tid] = src[(size_t)kk * WE];
                }
                {
                    const float* wb = sW + (c & 1) * KCH * 304;
                    const float* ab = sA + c * KCH * TROWS + rg * 4;
                    #pragma unroll
                    for (int kk = 0; kk < KCH; kk++) {
                        ull wpair = *(const ull*)&wb[kk * 304 + jj];
                        float wx, wy;
                        unpack2(wpair, wx, wy);
                        ull b0 = pack2(wx), b1v = pack2(wy);
                        ull a0 = *(const ull*)&ab[kk * TROWS];
                        ull a1 = *(const ull*)&ab[kk * TROWS + 2];
                        acc00 = ffma2(a0, b0,  acc00);
                        acc01 = ffma2(a0, b1v, acc01);
                        acc10 = ffma2(a1, b0,  acc10);
                        acc11 = ffma2(a1, b1v, acc11);
                    }
                }
                __syncthreads();
            }

            {
                int rbase = r0 + rg * 4;
                ull accs[2][2] = {{acc00, acc01}, {acc10, acc11}};
                #pragma unroll
                for (int p = 0; p < 2; p++) {
                    int rA = rbase + 2 * p;
                    #pragma unroll
                    for (int cc = 0; cc < 2; cc++) {
                        float lo, hi;
                        unpack2(accs[p][cc], lo, hi);
                        if (rA < cnt)
                            atomicAdd(&g_T[(size_t)rA * T_STRIDE + col0 + cc], lo);
                        if (rA + 1 < cnt)
                            atomicAdd(&g_T[(size_t)(rA + 1) * T_STRIDE + col0 + cc], hi);
                    }
                }
            }
            __syncthreads();
        } else {
            int w = task - ngemm;   // 0..8
            for (int t = tid; t < 150; t += 300) sA[t] = fmaxf(wt[w*150 + t], 0.f);
            __syncthreads();
            int g = tid / 150;
            int j = tid - g * 150;
            float acc = (g == 0) ? b1[j] : 0.f;
            int kst = g * 75;
            #pragma unroll 8
            for (int k = kst; k < kst + 75; k++)
                acc = fmaf(sA[k], W1[(size_t)(2*HH + k) * WE + j], acc);
            if (g == 1) sRed[j] = acc;
            __syncthreads();
            if (g == 0) g_WD[w * WD_STRIDE + j] = acc + sRed[j];
            __syncthreads();
        }
    }
}

// K5: unique rows -> h1 (gather+relu) -> @W23 + b23 -> logits + lse.
// Two-GEMM chain collapsed: logits = relu(h1) @ (W2@W3) + (b2@W3+b3).
// smem ~48 KB -> 3 CTAs/SM co-resident hide gather latency. Work-stealing.
// smem layout (floats): sW23[0,1800) sB23[1800,1812) sU[1812,11540) [64][152]
//                       sInfo[11540,11604) sTile[11604] sLg[11608,12376)
__global__ void __launch_bounds__(256, 3)
k_uniq()
{
    extern __shared__ float sm[];
    float* sW23 = sm;                    // [150][12]
    float* sB23 = sm + 1800;             // [12]
    float* sU   = sm + 1812;             // [64][152] row-major h1
    unsigned* sInfo = (unsigned*)(sm + 11540);  // [64]
    int* sTile = (int*)(sm + 11604);
    float* sLg = sm + 11608;             // [64][12]
    int tid = threadIdx.x;

    for (int t = tid; t < 150*12; t += 256) sW23[t] = g_W23[t];
    if (tid < 12) sB23[tid] = g_b23[tid];

    int nu = g_ucount;

    for (;;) {
        if (tid == 0) *sTile = atomicAdd(&g_tile, 1);
        __syncthreads();
        int base = (*sTile) * UT;
        if (base >= nu) break;

        if (tid < UT)
            sInfo[tid] = (base + tid < nu) ? g_uinfo[base + tid] : 0u;
        __syncthreads();

        // gather h1 row-major [r][152], float4 over k (cols 150,151 = 0)
        for (int idx = tid; idx < UT*38; idx += 256) {
            int r = idx / 38, kq = idx - r*38;
            unsigned info = sInfo[r];
            int ss = info & 0x3FFF, se = (info >> 14) & 0x3FFF, w = info >> 28;
            float4 ts = *(const float4*)&g_T[(size_t)ss*T_STRIDE + kq*4];
            float4 te = *(const float4*)&g_T[(size_t)se*T_STRIDE + 152 + kq*4];
            float4 wd = *(const float4*)&g_WD[w*WD_STRIDE + kq*4];
            float4 v;
            v.x = fmaxf(ts.x + te.x + wd.x, 0.f);
            v.y = fmaxf(ts.y + te.y + wd.y, 0.f);
            v.z = fmaxf(ts.z + te.z + wd.z, 0.f);
            v.w = fmaxf(ts.w + te.w + wd.w, 0.f);
            *(float4*)&sU[r*152 + kq*4] = v;
        }
        __syncthreads();

        // logits = h1 @ W23 + b23
        for (int idx = tid; idx < UT*LL; idx += 256) {
            int r = idx / LL, l = idx - r*LL;
            float a = sB23[l];
            #pragma unroll 5
            for (int k = 0; k < 150; k++)
                a = fmaf(sU[r*152 + k], sW23[k*12 + l], a);
            sLg[r*12 + l] = a;
            if (base + r < nu)
                g_ULOG[(size_t)(base + r)*12 + l] = a;
        }
        __syncthreads();

        // lse per unique row
        if (tid < UT && base + tid < nu) {
            float m = sLg[tid*12];
            #pragma unroll
            for (int l = 1; l < LL; l++) m = fmaxf(m, sLg[tid*12 + l]);
            float ssum = 0.f;
            #pragma unroll
            for (int l = 0; l < LL; l++) ssum += expf(sLg[tid*12 + l] - m);
            g_ULOG[(size_t)(base + tid)*12 + 9] = m + logf(ssum);
        }
        __syncthreads();
    }
}

// K6: scatter logits per span + NLL via precomputed lse + restore state
__global__ void k_scatter(const int* __restrict__ mask,
                          const int* __restrict__ label,
                          float* __restrict__ out)
{
    __shared__ float sL;
    if (threadIdx.x == 0) sL = 0.f;
    __syncthreads();
    int i = blockIdx.x * blockDim.x + threadIdx.x;
    float contrib = 0.f;
    if (i < NSPANS) {
        int key = g_key[i];
        int slot;
        if (key >= 0) { slot = g_uslot[key]; g_ckey[key] = 0; }
        else          { slot = g_spanslot[i]; }
        const float* Lr = &g_ULOG[(size_t)slot * 12];
        float4 p0 = *(const float4*)Lr;
        float4 p1 = *(const float4*)(Lr + 4);
        float2 p2 = *(const float2*)(Lr + 8);   // [8]=logit8, [9]=lse
        float L[9] = {p0.x, p0.y, p0.z, p0.w, p1.x, p1.y, p1.z, p1.w, p2.x};
        float* o = out + (size_t)i * LL;
        #pragma unroll
        for (int l = 0; l < LL; l++) o[l] = L[l];
        if (mask[i] == 1) {
            int lb = clampi(label[i], 0, LL-1);
            contrib = p2.y - L[lb];
        }
    }
    atomicAdd(&sL, contrib);
    __syncthreads();
    if (threadIdx.x == 0 && sL != 0.f)
        atomicAdd(&out[(size_t)NSPANS * LL], sL);
    if (blockIdx.x == 0 && threadIdx.x == 0) {
        g_count = 0; g_ucount = 0; g_tile = 0;
        #pragma unroll
        for (int w = 0; w < BB; w++) g_bcount[w] = 0;
    }
}

extern "C" void kernel_launch(void* const* d_in, const int* in_sizes, int n_in,
                              void* d_out, int out_size) {
    const float* seq = (const float*)d_in[0];
    const float* wt  = (const float*)d_in[1];
    const float* W1  = (const float*)d_in[2];
    const float* b1  = (const float*)d_in[3];
    const float* W2  = (const float*)d_in[4];
    const float* b2  = (const float*)d_in[5];
    const float* W3  = (const float*)d_in[6];
    const float* b3  = (const float*)d_in[7];
    const int* spans = (const int*)d_in[8];
    const int* smask = (const int*)d_in[9];
    const int* slab  = (const int*)d_in[10];
    float* out = (float*)d_out;

    static const size_t SMEM_UNIQ = (size_t)12376 * 4;   // 49504 B -> 3+ CTAs/SM
    static const size_t SMEM_TG   = (size_t)(2*KCH*304 + 96*TROWS + 8 + 160 + 8) * 4;
    cudaFuncSetAttribute(k_uniq, cudaFuncAttributeMaxDynamicSharedMemorySize, (int)SMEM_UNIQ);
    cudaFuncSetAttribute(k_TgemmWD, cudaFuncAttributeMaxDynamicSharedMemorySize, (int)SMEM_TG);

    k_mark<<<528, 256>>>(spans, W2, W3, b2, b3, out + (size_t)NSPANS * LL);
    k_compact<<<NPOS/256, 256>>>();
    k_claim<<<544, 256>>>(spans);
    k_TgemmWD<<<296, 300, SMEM_TG>>>(seq, W1, wt, b1);
    k_uniq<<<444, 256, SMEM_UNIQ>>>();
    k_scatter<<<NSPANS/256, 256>>>(smask, slab, out);
}